// round 1
// baseline (speedup 1.0000x reference)
#include <cuda_runtime.h>

#define NN 100000
#define EE 1600000
#define NBLK 98   // ceil(NN/1024)

// ---------------- scratch (static device allocations; no runtime alloc) ----------------
__device__ __align__(16) float g_h0[NN * 64];   // layer1 gemm out
__device__ __align__(16) float g_h1[NN * 64];   // layer1 aggregated + relu
__device__ __align__(16) float g_h2[NN * 40];   // layer2 gemm out
__device__ float g_adst[NN];
__device__ float g_asrc[NN];
__device__ int   g_rowptr[NN + 1];
__device__ int   g_cursor[NN];
__device__ int   g_col[EE];
__device__ int   g_bsum[128];

// ---------------- CSR build ----------------
__global__ void zero_int_kernel(int* __restrict__ p, int n) {
    int i = blockIdx.x * blockDim.x + threadIdx.x;
    if (i < n) p[i] = 0;
}

__global__ void hist_kernel(const int* __restrict__ ei, int* __restrict__ deg) {
    int e = blockIdx.x * blockDim.x + threadIdx.x;
    if (e < EE) atomicAdd(deg + ei[EE + e], 1);
}

__global__ void scan1_kernel(const int* __restrict__ deg, int* __restrict__ rowp,
                             int* __restrict__ bsum) {
    __shared__ int sh[1024];
    int tid = threadIdx.x;
    int i = blockIdx.x * 1024 + tid;
    int v = (i < NN) ? deg[i] : 0;
    sh[tid] = v;
    __syncthreads();
    for (int off = 1; off < 1024; off <<= 1) {
        int t = (tid >= off) ? sh[tid - off] : 0;
        __syncthreads();
        sh[tid] += t;
        __syncthreads();
    }
    if (i < NN) rowp[i] = sh[tid] - v;          // exclusive within block
    if (tid == 1023) bsum[blockIdx.x] = sh[1023];
}

__global__ void scan2_kernel(int* __restrict__ bsum) {
    __shared__ int sh[128];
    int tid = threadIdx.x;
    int v = (tid < NBLK) ? bsum[tid] : 0;
    sh[tid] = v;
    __syncthreads();
    for (int off = 1; off < 128; off <<= 1) {
        int t = (tid >= off) ? sh[tid - off] : 0;
        __syncthreads();
        sh[tid] += t;
        __syncthreads();
    }
    if (tid < NBLK) bsum[tid] = sh[tid] - v;    // exclusive block offsets
}

__global__ void scan3_kernel(int* __restrict__ rowp, const int* __restrict__ bsum,
                             int* __restrict__ cursor) {
    int i = blockIdx.x * blockDim.x + threadIdx.x;
    if (i < NN) {
        int r = rowp[i] + bsum[i >> 10];
        rowp[i] = r;
        cursor[i] = r;
    }
    if (i == 0) rowp[NN] = EE;
}

__global__ void scatter_kernel(const int* __restrict__ ei, int* __restrict__ cursor,
                               int* __restrict__ col) {
    int e = blockIdx.x * blockDim.x + threadIdx.x;
    if (e < EE) {
        int s = ei[e];
        int d = ei[EE + e];
        int p = atomicAdd(cursor + d, 1);
        col[p] = s;
    }
}

// ---------------- GEMM: C[N,CO] = A[N,K] @ W[CO,K]^T ----------------
// 128-node tile, 256 threads, micro-tile = 4 nodes x 8 channels, float4 along K.
// Smem rows are rotation-swizzled so fragment loads are bank-conflict-free.
template <int K, int CO>
__global__ void __launch_bounds__(256) gemm_kernel(const float* __restrict__ A,
                                                   const float* __restrict__ W,
                                                   float* __restrict__ C) {
    constexpr int K4 = K / 4;
    extern __shared__ float4 smem[];
    float4* xs = smem;             // 128 * K4
    float4* ws = smem + 128 * K4;  // 64  * K4 (rows >= CO zero-filled)

    int tid = threadIdx.x;
    int row0 = blockIdx.x * 128;

    for (int idx = tid; idx < 128 * K4; idx += 256) {
        int n = idx / K4, k4 = idx - n * K4;
        float4 v = make_float4(0.f, 0.f, 0.f, 0.f);
        int gn = row0 + n;
        if (gn < NN) v = reinterpret_cast<const float4*>(A)[gn * K4 + k4];
        xs[n * K4 + ((k4 + (n >> 2)) & (K4 - 1))] = v;
    }
    for (int idx = tid; idx < 64 * K4; idx += 256) {
        int c = idx / K4, k4 = idx - c * K4;
        float4 v = make_float4(0.f, 0.f, 0.f, 0.f);
        if (c < CO) v = reinterpret_cast<const float4*>(W)[c * K4 + k4];
        ws[c * K4 + ((k4 + (c >> 3)) & (K4 - 1))] = v;
    }
    __syncthreads();

    int tc = tid & 7;    // channel group (8 channels)
    int tn = tid >> 3;   // node group (4 nodes), 0..31

    float acc[4][8];
#pragma unroll
    for (int i = 0; i < 4; ++i)
#pragma unroll
        for (int j = 0; j < 8; ++j) acc[i][j] = 0.f;

#pragma unroll 4
    for (int k4 = 0; k4 < K4; ++k4) {
        float4 a[4], b[8];
        int ka = (k4 + tn) & (K4 - 1);
        int kb = (k4 + tc) & (K4 - 1);
#pragma unroll
        for (int i = 0; i < 4; ++i) a[i] = xs[(tn * 4 + i) * K4 + ka];
#pragma unroll
        for (int j = 0; j < 8; ++j) b[j] = ws[(tc * 8 + j) * K4 + kb];
#pragma unroll
        for (int i = 0; i < 4; ++i)
#pragma unroll
            for (int j = 0; j < 8; ++j) {
                acc[i][j] += a[i].x * b[j].x;
                acc[i][j] += a[i].y * b[j].y;
                acc[i][j] += a[i].z * b[j].z;
                acc[i][j] += a[i].w * b[j].w;
            }
    }

#pragma unroll
    for (int i = 0; i < 4; ++i) {
        int gn = row0 + tn * 4 + i;
        if (gn < NN) {
#pragma unroll
            for (int j = 0; j < 8; ++j) {
                int c = tc * 8 + j;
                if (c < CO) C[gn * CO + c] = acc[i][j];
            }
        }
    }
}

// ---------------- per-node attention coefficients ----------------
// adst[n] = dot(h[n], att[0:CH]); asrc[n] = dot(h[n], att[CH:2CH])
template <int CH>
__global__ void alpha_kernel(const float* __restrict__ h, const float* __restrict__ att,
                             float* __restrict__ adst, float* __restrict__ asrc) {
    int gw = (blockIdx.x * blockDim.x + threadIdx.x) >> 5;
    int lane = threadIdx.x & 31;
    if (gw >= NN) return;
    float h0v = (lane < CH) ? h[gw * CH + lane] : 0.f;
    float h1v = (lane + 32 < CH) ? h[gw * CH + lane + 32] : 0.f;
    float ai0 = (lane < CH) ? att[lane] : 0.f;
    float ai1 = (lane + 32 < CH) ? att[lane + 32] : 0.f;
    float aj0 = (lane < CH) ? att[CH + lane] : 0.f;
    float aj1 = (lane + 32 < CH) ? att[CH + lane + 32] : 0.f;
    float a0 = h0v * ai0 + h1v * ai1;
    float a1 = h0v * aj0 + h1v * aj1;
#pragma unroll
    for (int o = 16; o; o >>= 1) {
        a0 += __shfl_xor_sync(0xffffffffu, a0, o);
        a1 += __shfl_xor_sync(0xffffffffu, a1, o);
    }
    if (lane == 0) {
        adst[gw] = a0;
        asrc[gw] = a1;
    }
}

// ---------------- fused segment softmax + aggregation (warp per dst) ----------------
__device__ __forceinline__ float lrelu(float x) { return x < 0.f ? 0.2f * x : x; }

template <int CH, bool RELU, bool LSM>
__global__ void aggregate_kernel(const float* __restrict__ h, const float* __restrict__ adst,
                                 const float* __restrict__ asrc, const int* __restrict__ rowp,
                                 const int* __restrict__ col, float* __restrict__ out) {
    int d = (blockIdx.x * blockDim.x + threadIdx.x) >> 5;
    int lane = threadIdx.x & 31;
    if (d >= NN) return;

    int rs = rowp[d], re = rowp[d + 1];
    float ad = adst[d];
    float lself = lrelu(ad + asrc[d]);  // implicit self-loop

    // pass 1: segment max (lane-parallel)
    float lm = lself;
    for (int i = rs + lane; i < re; i += 32)
        lm = fmaxf(lm, lrelu(ad + asrc[col[i]]));
#pragma unroll
    for (int o = 16; o; o >>= 1) lm = fmaxf(lm, __shfl_xor_sync(0xffffffffu, lm, o));

    // pass 2: exp-sum + weighted feature gather
    const bool hi = (lane + 32) < CH;
    float acc0 = 0.f, acc1 = 0.f, psum = 0.f;
    for (int base = rs; base < re; base += 32) {
        int i = base + lane;
        int s = 0;
        float e = 0.f;
        if (i < re) {
            s = col[i];
            e = __expf(lrelu(ad + asrc[s]) - lm);
        }
        psum += e;
        int cnt = min(32, re - base);
        for (int j = 0; j < cnt; ++j) {
            float ej = __shfl_sync(0xffffffffu, e, j);
            int sj = __shfl_sync(0xffffffffu, s, j);
            acc0 += ej * h[sj * CH + lane];
            if (CH > 32 && hi) acc1 += ej * h[sj * CH + lane + 32];
        }
    }
#pragma unroll
    for (int o = 16; o; o >>= 1) psum += __shfl_xor_sync(0xffffffffu, psum, o);

    // self loop contribution
    float es = __expf(lself - lm);
    psum += es;
    acc0 += es * h[d * CH + lane];
    if (CH > 32 && hi) acc1 += es * h[d * CH + lane + 32];

    float inv = 1.0f / psum;
    float v0 = acc0 * inv;
    float v1 = acc1 * inv;

    if (LSM) {
        // fused log_softmax over CH classes (values already in registers)
        float vm = hi ? fmaxf(v0, v1) : v0;
#pragma unroll
        for (int o = 16; o; o >>= 1) vm = fmaxf(vm, __shfl_xor_sync(0xffffffffu, vm, o));
        float se = __expf(v0 - vm) + (hi ? __expf(v1 - vm) : 0.f);
#pragma unroll
        for (int o = 16; o; o >>= 1) se += __shfl_xor_sync(0xffffffffu, se, o);
        float l = vm + logf(se);
        out[d * CH + lane] = v0 - l;
        if (hi) out[d * CH + lane + 32] = v1 - l;
    } else {
        if (RELU) {
            v0 = fmaxf(v0, 0.f);
            v1 = fmaxf(v1, 0.f);
        }
        out[d * CH + lane] = v0;
        if (CH > 32 && hi) out[d * CH + lane + 32] = v1;
    }
}

// ---------------- launch ----------------
extern "C" void kernel_launch(void* const* d_in, const int* in_sizes, int n_in,
                              void* d_out, int out_size) {
    (void)in_sizes;
    (void)n_in;
    (void)out_size;
    const float* x    = (const float*)d_in[0];
    const int*   ei   = (const int*)d_in[1];
    const float* W0   = (const float*)d_in[2];
    const float* att0 = (const float*)d_in[3];
    const float* W1   = (const float*)d_in[4];
    const float* att1 = (const float*)d_in[5];
    float* out = (float*)d_out;

    void *p;
    float *h0, *h1, *h2, *adst, *asrc;
    int *rowptr, *cursor, *colp, *bsum;
    cudaGetSymbolAddress(&p, g_h0);     h0 = (float*)p;
    cudaGetSymbolAddress(&p, g_h1);     h1 = (float*)p;
    cudaGetSymbolAddress(&p, g_h2);     h2 = (float*)p;
    cudaGetSymbolAddress(&p, g_adst);   adst = (float*)p;
    cudaGetSymbolAddress(&p, g_asrc);   asrc = (float*)p;
    cudaGetSymbolAddress(&p, g_rowptr); rowptr = (int*)p;
    cudaGetSymbolAddress(&p, g_cursor); cursor = (int*)p;
    cudaGetSymbolAddress(&p, g_col);    colp = (int*)p;
    cudaGetSymbolAddress(&p, g_bsum);   bsum = (int*)p;

    cudaFuncSetAttribute(gemm_kernel<128, 64>,
                         cudaFuncAttributeMaxDynamicSharedMemorySize, 98304);
    cudaFuncSetAttribute(gemm_kernel<64, 40>,
                         cudaFuncAttributeMaxDynamicSharedMemorySize, 49152);

    const int TB = 256;
    // CSR build (shared by both layers; self-loops handled implicitly)
    zero_int_kernel<<<(NN + TB - 1) / TB, TB>>>(cursor, NN);
    hist_kernel<<<(EE + TB - 1) / TB, TB>>>(ei, cursor);
    scan1_kernel<<<NBLK, 1024>>>(cursor, rowptr, bsum);
    scan2_kernel<<<1, 128>>>(bsum);
    scan3_kernel<<<(NN + TB - 1) / TB, TB>>>(rowptr, bsum, cursor);
    scatter_kernel<<<(EE + TB - 1) / TB, TB>>>(ei, cursor, colp);

    int gemm_blocks = (NN + 127) / 128;        // 782
    int warp_blocks = (NN * 32 + TB - 1) / TB; // 12500

    // Layer 1: 128 -> 64, relu
    gemm_kernel<128, 64><<<gemm_blocks, TB, 98304>>>(x, W0, h0);
    alpha_kernel<64><<<warp_blocks, TB>>>(h0, att0, adst, asrc);
    aggregate_kernel<64, true, false><<<warp_blocks, TB>>>(h0, adst, asrc, rowptr, colp, h1);

    // Layer 2: 64 -> 40, fused log_softmax
    gemm_kernel<64, 40><<<gemm_blocks, TB, 49152>>>(h1, W1, h2);
    alpha_kernel<40><<<warp_blocks, TB>>>(h2, att1, adst, asrc);
    aggregate_kernel<40, false, true><<<warp_blocks, TB>>>(h2, adst, asrc, rowptr, colp, out);
}

// round 2
// speedup vs baseline: 1.0525x; 1.0525x over previous
#include <cuda_runtime.h>

#define NN 100000
#define EE 1600000
#define NBLK 98   // ceil(NN/1024)

// ---------------- scratch (static device allocations; no runtime alloc) ----------------
__device__ __align__(16) float g_h0[NN * 64];   // layer1 gemm out
__device__ __align__(16) float g_h1[NN * 64];   // layer1 aggregated + relu
__device__ __align__(16) float g_h2[NN * 40];   // layer2 gemm out
__device__ float g_adst[NN];
__device__ float g_asrc[NN];
__device__ int   g_rowptr[NN + 1];
__device__ int   g_cursor[NN];
__device__ int   g_col[EE];
__device__ int   g_bsum[128];

// ---------------- CSR build ----------------
__global__ void zero_int_kernel(int* __restrict__ p, int n) {
    int i = blockIdx.x * blockDim.x + threadIdx.x;
    if (i < n) p[i] = 0;
}

__global__ void hist_kernel(const int* __restrict__ ei, int* __restrict__ deg) {
    int e = blockIdx.x * blockDim.x + threadIdx.x;
    if (e < EE) atomicAdd(deg + __ldg(ei + EE + e), 1);
}

__global__ void scan1_kernel(const int* __restrict__ deg, int* __restrict__ rowp,
                             int* __restrict__ bsum) {
    __shared__ int sh[1024];
    int tid = threadIdx.x;
    int i = blockIdx.x * 1024 + tid;
    int v = (i < NN) ? deg[i] : 0;
    sh[tid] = v;
    __syncthreads();
    for (int off = 1; off < 1024; off <<= 1) {
        int t = (tid >= off) ? sh[tid - off] : 0;
        __syncthreads();
        sh[tid] += t;
        __syncthreads();
    }
    if (i < NN) rowp[i] = sh[tid] - v;          // exclusive within block
    if (tid == 1023) bsum[blockIdx.x] = sh[1023];
}

__global__ void scan2_kernel(int* __restrict__ bsum) {
    __shared__ int sh[128];
    int tid = threadIdx.x;
    int v = (tid < NBLK) ? bsum[tid] : 0;
    sh[tid] = v;
    __syncthreads();
    for (int off = 1; off < 128; off <<= 1) {
        int t = (tid >= off) ? sh[tid - off] : 0;
        __syncthreads();
        sh[tid] += t;
        __syncthreads();
    }
    if (tid < NBLK) bsum[tid] = sh[tid] - v;    // exclusive block offsets
}

__global__ void scan3_kernel(int* __restrict__ rowp, const int* __restrict__ bsum,
                             int* __restrict__ cursor) {
    int i = blockIdx.x * blockDim.x + threadIdx.x;
    if (i < NN) {
        int r = rowp[i] + bsum[i >> 10];
        rowp[i] = r;
        cursor[i] = r;
    }
    if (i == 0) rowp[NN] = EE;
}

__global__ void scatter_kernel(const int* __restrict__ ei, int* __restrict__ cursor,
                               int* __restrict__ col) {
    int e = blockIdx.x * blockDim.x + threadIdx.x;
    if (e < EE) {
        int s = __ldg(ei + e);
        int d = __ldg(ei + EE + e);
        int p = atomicAdd(cursor + d, 1);
        col[p] = s;
    }
}

// ---------------- GEMM: C[N,CO] = A[N,K] @ W[CO,K]^T, fused alpha epilogue -----------
// 128-node tile, 256 threads, micro-tile = 4 nodes x 8 channels, float4 along K.
// Smem rows are rotation-swizzled so fragment loads are bank-conflict-free.
// Epilogue also computes adst[n] = dot(C[n], att[0:CO]), asrc[n] = dot(C[n], att[CO:2CO]).
template <int K, int CO>
__global__ void __launch_bounds__(256) gemm_kernel(const float* __restrict__ A,
                                                   const float* __restrict__ W,
                                                   const float* __restrict__ att,
                                                   float* __restrict__ C,
                                                   float* __restrict__ adst,
                                                   float* __restrict__ asrc) {
    constexpr int K4 = K / 4;
    extern __shared__ float4 smem[];
    float4* xs = smem;             // 128 * K4
    float4* ws = smem + 128 * K4;  // 64  * K4 (rows >= CO zero-filled)

    int tid = threadIdx.x;
    int row0 = blockIdx.x * 128;

    for (int idx = tid; idx < 128 * K4; idx += 256) {
        int n = idx / K4, k4 = idx - n * K4;
        float4 v = make_float4(0.f, 0.f, 0.f, 0.f);
        int gn = row0 + n;
        if (gn < NN) v = reinterpret_cast<const float4*>(A)[gn * K4 + k4];
        xs[n * K4 + ((k4 + (n >> 2)) & (K4 - 1))] = v;
    }
    for (int idx = tid; idx < 64 * K4; idx += 256) {
        int c = idx / K4, k4 = idx - c * K4;
        float4 v = make_float4(0.f, 0.f, 0.f, 0.f);
        if (c < CO) v = reinterpret_cast<const float4*>(W)[c * K4 + k4];
        ws[c * K4 + ((k4 + (c >> 3)) & (K4 - 1))] = v;
    }
    __syncthreads();

    int tc = tid & 7;    // channel group (8 channels)
    int tn = tid >> 3;   // node group (4 nodes), 0..31

    float acc[4][8];
#pragma unroll
    for (int i = 0; i < 4; ++i)
#pragma unroll
        for (int j = 0; j < 8; ++j) acc[i][j] = 0.f;

#pragma unroll 4
    for (int k4 = 0; k4 < K4; ++k4) {
        float4 a[4], b[8];
        int ka = (k4 + tn) & (K4 - 1);
        int kb = (k4 + tc) & (K4 - 1);
#pragma unroll
        for (int i = 0; i < 4; ++i) a[i] = xs[(tn * 4 + i) * K4 + ka];
#pragma unroll
        for (int j = 0; j < 8; ++j) b[j] = ws[(tc * 8 + j) * K4 + kb];
#pragma unroll
        for (int i = 0; i < 4; ++i)
#pragma unroll
            for (int j = 0; j < 8; ++j) {
                acc[i][j] += a[i].x * b[j].x;
                acc[i][j] += a[i].y * b[j].y;
                acc[i][j] += a[i].z * b[j].z;
                acc[i][j] += a[i].w * b[j].w;
            }
    }

    // store C
#pragma unroll
    for (int i = 0; i < 4; ++i) {
        int gn = row0 + tn * 4 + i;
        if (gn < NN) {
#pragma unroll
            for (int j = 0; j < 8; ++j) {
                int c = tc * 8 + j;
                if (c < CO) C[gn * CO + c] = acc[i][j];
            }
        }
    }

    // fused alpha epilogue: per-node dots with att, reduced across the 8 tc lanes
    float ai[8], aj[8];
#pragma unroll
    for (int j = 0; j < 8; ++j) {
        int c = tc * 8 + j;
        ai[j] = (c < CO) ? __ldg(att + c) : 0.f;
        aj[j] = (c < CO) ? __ldg(att + CO + c) : 0.f;
    }
    float pd[4], ps[4];
#pragma unroll
    for (int i = 0; i < 4; ++i) {
        pd[i] = 0.f;
        ps[i] = 0.f;
#pragma unroll
        for (int j = 0; j < 8; ++j) {
            pd[i] += acc[i][j] * ai[j];
            ps[i] += acc[i][j] * aj[j];
        }
    }
#pragma unroll
    for (int o = 4; o; o >>= 1) {
#pragma unroll
        for (int i = 0; i < 4; ++i) {
            pd[i] += __shfl_xor_sync(0xffffffffu, pd[i], o);
            ps[i] += __shfl_xor_sync(0xffffffffu, ps[i], o);
        }
    }
    if (tc == 0) {
#pragma unroll
        for (int i = 0; i < 4; ++i) {
            int gn = row0 + tn * 4 + i;
            if (gn < NN) {
                adst[gn] = pd[i];
                asrc[gn] = ps[i];
            }
        }
    }
}

// ---------------- fused segment softmax + aggregation (warp per dst) ----------------
// Single pass: logits are tiny (|l| < ~10), so exp without max-subtraction is safe
// and alpha = e/sum(e) is shift-invariant (matches reference exactly in exact math).
__device__ __forceinline__ float lrelu(float x) { return x < 0.f ? 0.2f * x : x; }

template <int CH, bool RELU, bool LSM>
__global__ void aggregate_kernel(const float* __restrict__ h, const float* __restrict__ adst,
                                 const float* __restrict__ asrc, const int* __restrict__ rowp,
                                 const int* __restrict__ col, float* __restrict__ out) {
    constexpr int NL = CH / 4;    // lanes holding one float4 of channels (16 or 10)
    constexpr int NS = 32 / NL;   // sources processed per broadcast step (2 or 3)

    int d = (blockIdx.x * blockDim.x + threadIdx.x) >> 5;
    int lane = threadIdx.x & 31;
    if (d >= NN) return;

    int rs = __ldg(rowp + d), re = __ldg(rowp + d + 1);
    float ad = adst[d];

    int group = lane / NL;
    int cid = lane - group * NL;
    bool act = group < NS;

    const float4* __restrict__ h4 = reinterpret_cast<const float4*>(h);

    float4 acc = make_float4(0.f, 0.f, 0.f, 0.f);
    float psum = 0.f;

    for (int base = rs; base < re; base += 32) {
        int i = base + lane;
        int s = 0;
        float e = 0.f;
        if (i < re) {
            s = col[i];
            e = __expf(lrelu(ad + __ldg(asrc + s)));
        }
        psum += e;
        int cnt = min(32, re - base);
        for (int j = 0; j < cnt; j += NS) {
            int pj = j + group;
            float ej = __shfl_sync(0xffffffffu, e, pj & 31);
            int sj = __shfl_sync(0xffffffffu, s, pj & 31);
            if (!act || pj >= cnt) ej = 0.f;
            float4 hv = h4[(size_t)sj * NL + cid];
            acc.x += ej * hv.x;
            acc.y += ej * hv.y;
            acc.z += ej * hv.z;
            acc.w += ej * hv.w;
        }
    }

    // reduce psum across warp
#pragma unroll
    for (int o = 16; o; o >>= 1) psum += __shfl_xor_sync(0xffffffffu, psum, o);

    // reduce acc across source groups onto lanes [0, NL)
#pragma unroll
    for (int g = 1; g < NS; ++g) {
        int srcl = cid + g * NL;
        float tx = __shfl_sync(0xffffffffu, acc.x, srcl & 31);
        float ty = __shfl_sync(0xffffffffu, acc.y, srcl & 31);
        float tz = __shfl_sync(0xffffffffu, acc.z, srcl & 31);
        float tw = __shfl_sync(0xffffffffu, acc.w, srcl & 31);
        if (lane < NL) {
            acc.x += tx;
            acc.y += ty;
            acc.z += tz;
            acc.w += tw;
        }
    }

    // implicit self-loop
    float es = __expf(lrelu(ad + __ldg(asrc + d)));
    psum += es;

    float4 v = make_float4(0.f, 0.f, 0.f, 0.f);
    if (lane < NL) {
        float4 hv = h4[(size_t)d * NL + cid];
        float inv = 1.0f / psum;
        v.x = (acc.x + es * hv.x) * inv;
        v.y = (acc.y + es * hv.y) * inv;
        v.z = (acc.z + es * hv.z) * inv;
        v.w = (acc.w + es * hv.w) * inv;
    }

    if (LSM) {
        // fused log_softmax over CH classes
        float vm = -1e30f;
        if (lane < NL) vm = fmaxf(fmaxf(v.x, v.y), fmaxf(v.z, v.w));
#pragma unroll
        for (int o = 16; o; o >>= 1) vm = fmaxf(vm, __shfl_xor_sync(0xffffffffu, vm, o));
        float se = 0.f;
        if (lane < NL)
            se = __expf(v.x - vm) + __expf(v.y - vm) + __expf(v.z - vm) + __expf(v.w - vm);
#pragma unroll
        for (int o = 16; o; o >>= 1) se += __shfl_xor_sync(0xffffffffu, se, o);
        float l = vm + logf(se);
        if (lane < NL) {
            v.x -= l;
            v.y -= l;
            v.z -= l;
            v.w -= l;
            reinterpret_cast<float4*>(out)[(size_t)d * NL + cid] = v;
        }
    } else {
        if (lane < NL) {
            if (RELU) {
                v.x = fmaxf(v.x, 0.f);
                v.y = fmaxf(v.y, 0.f);
                v.z = fmaxf(v.z, 0.f);
                v.w = fmaxf(v.w, 0.f);
            }
            reinterpret_cast<float4*>(out)[(size_t)d * NL + cid] = v;
        }
    }
}

// ---------------- launch ----------------
extern "C" void kernel_launch(void* const* d_in, const int* in_sizes, int n_in,
                              void* d_out, int out_size) {
    (void)in_sizes;
    (void)n_in;
    (void)out_size;
    const float* x    = (const float*)d_in[0];
    const int*   ei   = (const int*)d_in[1];
    const float* W0   = (const float*)d_in[2];
    const float* att0 = (const float*)d_in[3];
    const float* W1   = (const float*)d_in[4];
    const float* att1 = (const float*)d_in[5];
    float* out = (float*)d_out;

    void *p;
    float *h0, *h1, *h2, *adst, *asrc;
    int *rowptr, *cursor, *colp, *bsum;
    cudaGetSymbolAddress(&p, g_h0);     h0 = (float*)p;
    cudaGetSymbolAddress(&p, g_h1);     h1 = (float*)p;
    cudaGetSymbolAddress(&p, g_h2);     h2 = (float*)p;
    cudaGetSymbolAddress(&p, g_adst);   adst = (float*)p;
    cudaGetSymbolAddress(&p, g_asrc);   asrc = (float*)p;
    cudaGetSymbolAddress(&p, g_rowptr); rowptr = (int*)p;
    cudaGetSymbolAddress(&p, g_cursor); cursor = (int*)p;
    cudaGetSymbolAddress(&p, g_col);    colp = (int*)p;
    cudaGetSymbolAddress(&p, g_bsum);   bsum = (int*)p;

    cudaFuncSetAttribute(gemm_kernel<128, 64>,
                         cudaFuncAttributeMaxDynamicSharedMemorySize, 98304);
    cudaFuncSetAttribute(gemm_kernel<64, 40>,
                         cudaFuncAttributeMaxDynamicSharedMemorySize, 49152);

    const int TB = 256;
    // CSR build (shared by both layers; self-loops handled implicitly)
    zero_int_kernel<<<(NN + TB - 1) / TB, TB>>>(cursor, NN);
    hist_kernel<<<(EE + TB - 1) / TB, TB>>>(ei, cursor);
    scan1_kernel<<<NBLK, 1024>>>(cursor, rowptr, bsum);
    scan2_kernel<<<1, 128>>>(bsum);
    scan3_kernel<<<(NN + TB - 1) / TB, TB>>>(rowptr, bsum, cursor);
    scatter_kernel<<<(EE + TB - 1) / TB, TB>>>(ei, cursor, colp);

    int gemm_blocks = (NN + 127) / 128;        // 782
    int warp_blocks = (NN * 32 + TB - 1) / TB; // 12500

    // Layer 1: 128 -> 64, relu
    gemm_kernel<128, 64><<<gemm_blocks, TB, 98304>>>(x, W0, att0, h0, adst, asrc);
    aggregate_kernel<64, true, false><<<warp_blocks, TB>>>(h0, adst, asrc, rowptr, colp, h1);

    // Layer 2: 64 -> 40, fused log_softmax
    gemm_kernel<64, 40><<<gemm_blocks, TB, 49152>>>(h1, W1, att1, h2, adst, asrc);
    aggregate_kernel<40, false, true><<<warp_blocks, TB>>>(h2, adst, asrc, rowptr, colp, out);
}

// round 3
// speedup vs baseline: 1.0920x; 1.0375x over previous
#include <cuda_runtime.h>

#define NN 100000
#define EE 1600000
#define NBLK 98          // ceil(NN/1024)
#define HB  1563         // hist blocks: ceil(EE/4/256)
#define GB1 782          // gemm1 blocks: ceil(NN/128)

// ---------------- scratch (static device allocations; no runtime alloc) ----------------
__device__ __align__(16) float g_h0[NN * 64];   // layer1 gemm out
__device__ __align__(16) float g_h1[NN * 64];   // layer1 aggregated + relu
__device__ __align__(16) float g_h2[NN * 40];   // layer2 gemm out
__device__ float g_adst[NN];
__device__ float g_asrc[NN];
__device__ int   g_rowptr[NN + 1];
__device__ int   g_cursor[NN];
__device__ int   g_col[EE];
__device__ int   g_bsum[128];

// ---------------- GEMM body: C[N,CO] = A[N,K] @ W[CO,K]^T, fused alpha epilogue -------
// 128-node tile, 256 threads, micro-tile = 4 nodes x 8 channels, float4 along K.
// Smem rows are rotation-swizzled so fragment loads are bank-conflict-free.
// Epilogue also computes adst[n] = dot(C[n], att[0:CO]), asrc[n] = dot(C[n], att[CO:2CO]).
template <int K, int CO>
__device__ __forceinline__ void gemm_body(int bid, const float* __restrict__ A,
                                          const float* __restrict__ W,
                                          const float* __restrict__ att,
                                          float* __restrict__ C,
                                          float* __restrict__ adst,
                                          float* __restrict__ asrc) {
    constexpr int K4 = K / 4;
    extern __shared__ float4 smem[];
    float4* xs = smem;             // 128 * K4
    float4* ws = smem + 128 * K4;  // 64  * K4 (rows >= CO zero-filled)

    int tid = threadIdx.x;
    int row0 = bid * 128;

    for (int idx = tid; idx < 128 * K4; idx += 256) {
        int n = idx / K4, k4 = idx - n * K4;
        float4 v = make_float4(0.f, 0.f, 0.f, 0.f);
        int gn = row0 + n;
        if (gn < NN) v = reinterpret_cast<const float4*>(A)[gn * K4 + k4];
        xs[n * K4 + ((k4 + (n >> 2)) & (K4 - 1))] = v;
    }
    for (int idx = tid; idx < 64 * K4; idx += 256) {
        int c = idx / K4, k4 = idx - c * K4;
        float4 v = make_float4(0.f, 0.f, 0.f, 0.f);
        if (c < CO) v = reinterpret_cast<const float4*>(W)[c * K4 + k4];
        ws[c * K4 + ((k4 + (c >> 3)) & (K4 - 1))] = v;
    }
    __syncthreads();

    int tc = tid & 7;    // channel group (8 channels)
    int tn = tid >> 3;   // node group (4 nodes), 0..31

    float acc[4][8];
#pragma unroll
    for (int i = 0; i < 4; ++i)
#pragma unroll
        for (int j = 0; j < 8; ++j) acc[i][j] = 0.f;

#pragma unroll 4
    for (int k4 = 0; k4 < K4; ++k4) {
        float4 a[4], b[8];
        int ka = (k4 + tn) & (K4 - 1);
        int kb = (k4 + tc) & (K4 - 1);
#pragma unroll
        for (int i = 0; i < 4; ++i) a[i] = xs[(tn * 4 + i) * K4 + ka];
#pragma unroll
        for (int j = 0; j < 8; ++j) b[j] = ws[(tc * 8 + j) * K4 + kb];
#pragma unroll
        for (int i = 0; i < 4; ++i)
#pragma unroll
            for (int j = 0; j < 8; ++j) {
                acc[i][j] += a[i].x * b[j].x;
                acc[i][j] += a[i].y * b[j].y;
                acc[i][j] += a[i].z * b[j].z;
                acc[i][j] += a[i].w * b[j].w;
            }
    }

    // store C
#pragma unroll
    for (int i = 0; i < 4; ++i) {
        int gn = row0 + tn * 4 + i;
        if (gn < NN) {
#pragma unroll
            for (int j = 0; j < 8; ++j) {
                int c = tc * 8 + j;
                if (c < CO) C[gn * CO + c] = acc[i][j];
            }
        }
    }

    // fused alpha epilogue: per-node dots with att, reduced across the 8 tc lanes
    float ai[8], aj[8];
#pragma unroll
    for (int j = 0; j < 8; ++j) {
        int c = tc * 8 + j;
        ai[j] = (c < CO) ? __ldg(att + c) : 0.f;
        aj[j] = (c < CO) ? __ldg(att + CO + c) : 0.f;
    }
    float pd[4], ps[4];
#pragma unroll
    for (int i = 0; i < 4; ++i) {
        pd[i] = 0.f;
        ps[i] = 0.f;
#pragma unroll
        for (int j = 0; j < 8; ++j) {
            pd[i] += acc[i][j] * ai[j];
            ps[i] += acc[i][j] * aj[j];
        }
    }
#pragma unroll
    for (int o = 4; o; o >>= 1) {
#pragma unroll
        for (int i = 0; i < 4; ++i) {
            pd[i] += __shfl_xor_sync(0xffffffffu, pd[i], o);
            ps[i] += __shfl_xor_sync(0xffffffffu, ps[i], o);
        }
    }
    if (tc == 0) {
#pragma unroll
        for (int i = 0; i < 4; ++i) {
            int gn = row0 + tn * 4 + i;
            if (gn < NN) {
                adst[gn] = pd[i];
                asrc[gn] = ps[i];
            }
        }
    }
}

// ---------------- fused gemm1 + degree histogram ----------------
// Blocks [0, HB) compute the dst-degree histogram (independent of the GEMM);
// blocks [HB, HB+GB1) run the layer-1 GEMM. Hist is atomic-latency bound with
// near-zero issue pressure, so it hides completely under the FFMA-bound GEMM.
__global__ void __launch_bounds__(256) gemm1_hist_kernel(const float* __restrict__ A,
                                                         const float* __restrict__ W,
                                                         const float* __restrict__ att,
                                                         float* __restrict__ C,
                                                         float* __restrict__ adst,
                                                         float* __restrict__ asrc,
                                                         const int* __restrict__ ei,
                                                         int* __restrict__ deg) {
    if (blockIdx.x < HB) {
        int t = blockIdx.x * 256 + threadIdx.x;
        if (t < EE / 4) {
            int4 d4 = reinterpret_cast<const int4*>(ei + EE)[t];
            atomicAdd(deg + d4.x, 1);
            atomicAdd(deg + d4.y, 1);
            atomicAdd(deg + d4.z, 1);
            atomicAdd(deg + d4.w, 1);
        }
        return;
    }
    gemm_body<128, 64>(blockIdx.x - HB, A, W, att, C, adst, asrc);
}

__global__ void __launch_bounds__(256) gemm2_kernel(const float* __restrict__ A,
                                                    const float* __restrict__ W,
                                                    const float* __restrict__ att,
                                                    float* __restrict__ C,
                                                    float* __restrict__ adst,
                                                    float* __restrict__ asrc) {
    gemm_body<64, 40>(blockIdx.x, A, W, att, C, adst, asrc);
}

// ---------------- CSR build ----------------
__global__ void scan1_kernel(const int* __restrict__ deg, int* __restrict__ rowp,
                             int* __restrict__ bsum) {
    __shared__ int sh[1024];
    int tid = threadIdx.x;
    int i = blockIdx.x * 1024 + tid;
    int v = (i < NN) ? deg[i] : 0;
    sh[tid] = v;
    __syncthreads();
    for (int off = 1; off < 1024; off <<= 1) {
        int t = (tid >= off) ? sh[tid - off] : 0;
        __syncthreads();
        sh[tid] += t;
        __syncthreads();
    }
    if (i < NN) rowp[i] = sh[tid] - v;          // exclusive within block
    if (tid == 1023) bsum[blockIdx.x] = sh[1023];
}

// fused scan2+scan3: each block computes its own bsum prefix, then applies offset
__global__ void scan23_kernel(int* __restrict__ rowp, const int* __restrict__ bsum,
                              int* __restrict__ cursor) {
    __shared__ int soff;
    int tid = threadIdx.x;
    if (tid == 0) soff = 0;
    __syncthreads();
    if (tid < blockIdx.x) atomicAdd(&soff, bsum[tid]);   // blockIdx.x < NBLK <= 98
    __syncthreads();
    int off = soff;
    int i = blockIdx.x * 1024 + tid;
    if (i < NN) {
        int r = rowp[i] + off;
        rowp[i] = r;
        cursor[i] = r;
    }
    if (i == 0) rowp[NN] = EE;
}

__global__ void scatter_kernel(const int* __restrict__ ei, int* __restrict__ cursor,
                               int* __restrict__ col) {
    int t = blockIdx.x * blockDim.x + threadIdx.x;
    if (t < EE / 4) {
        int4 s4 = reinterpret_cast<const int4*>(ei)[t];
        int4 d4 = reinterpret_cast<const int4*>(ei + EE)[t];
        int p;
        p = atomicAdd(cursor + d4.x, 1); col[p] = s4.x;
        p = atomicAdd(cursor + d4.y, 1); col[p] = s4.y;
        p = atomicAdd(cursor + d4.z, 1); col[p] = s4.z;
        p = atomicAdd(cursor + d4.w, 1); col[p] = s4.w;
    }
}

// ---------------- fused segment softmax + aggregation (warp per dst) ----------------
// Single pass: logits are tiny (|l| < ~10), so exp without max-subtraction is safe
// and alpha = e/sum(e) is shift-invariant (matches reference exactly in exact math).
__device__ __forceinline__ float lrelu(float x) { return x < 0.f ? 0.2f * x : x; }

template <int CH, bool RELU, bool LSM>
__global__ void aggregate_kernel(const float* __restrict__ h, const float* __restrict__ adst,
                                 const float* __restrict__ asrc, const int* __restrict__ rowp,
                                 const int* __restrict__ col, float* __restrict__ out) {
    constexpr int NL = CH / 4;    // lanes holding one float4 of channels (16 or 10)
    constexpr int NS = 32 / NL;   // sources processed per broadcast step (2 or 3)

    int d = (blockIdx.x * blockDim.x + threadIdx.x) >> 5;
    int lane = threadIdx.x & 31;
    if (d >= NN) return;

    int rs = __ldg(rowp + d), re = __ldg(rowp + d + 1);
    float ad = adst[d];

    int group = lane / NL;
    int cid = lane - group * NL;
    bool act = group < NS;

    const float4* __restrict__ h4 = reinterpret_cast<const float4*>(h);

    float4 acc = make_float4(0.f, 0.f, 0.f, 0.f);
    float psum = 0.f;

    for (int base = rs; base < re; base += 32) {
        int i = base + lane;
        int s = 0;
        float e = 0.f;
        if (i < re) {
            s = col[i];
            e = __expf(lrelu(ad + __ldg(asrc + s)));
        }
        psum += e;
        int cnt = min(32, re - base);
        for (int j = 0; j < cnt; j += NS) {
            int pj = j + group;
            float ej = __shfl_sync(0xffffffffu, e, pj & 31);
            int sj = __shfl_sync(0xffffffffu, s, pj & 31);
            if (!act || pj >= cnt) ej = 0.f;
            float4 hv = h4[(size_t)sj * NL + cid];
            acc.x += ej * hv.x;
            acc.y += ej * hv.y;
            acc.z += ej * hv.z;
            acc.w += ej * hv.w;
        }
    }

    // reduce psum across warp
#pragma unroll
    for (int o = 16; o; o >>= 1) psum += __shfl_xor_sync(0xffffffffu, psum, o);

    // reduce acc across source groups onto lanes [0, NL)
#pragma unroll
    for (int g = 1; g < NS; ++g) {
        int srcl = cid + g * NL;
        float tx = __shfl_sync(0xffffffffu, acc.x, srcl & 31);
        float ty = __shfl_sync(0xffffffffu, acc.y, srcl & 31);
        float tz = __shfl_sync(0xffffffffu, acc.z, srcl & 31);
        float tw = __shfl_sync(0xffffffffu, acc.w, srcl & 31);
        if (lane < NL) {
            acc.x += tx;
            acc.y += ty;
            acc.z += tz;
            acc.w += tw;
        }
    }

    // implicit self-loop
    float es = __expf(lrelu(ad + __ldg(asrc + d)));
    psum += es;

    float4 v = make_float4(0.f, 0.f, 0.f, 0.f);
    if (lane < NL) {
        float4 hv = h4[(size_t)d * NL + cid];
        float inv = 1.0f / psum;
        v.x = (acc.x + es * hv.x) * inv;
        v.y = (acc.y + es * hv.y) * inv;
        v.z = (acc.z + es * hv.z) * inv;
        v.w = (acc.w + es * hv.w) * inv;
    }

    if (LSM) {
        // fused log_softmax over CH classes
        float vm = -1e30f;
        if (lane < NL) vm = fmaxf(fmaxf(v.x, v.y), fmaxf(v.z, v.w));
#pragma unroll
        for (int o = 16; o; o >>= 1) vm = fmaxf(vm, __shfl_xor_sync(0xffffffffu, vm, o));
        float se = 0.f;
        if (lane < NL)
            se = __expf(v.x - vm) + __expf(v.y - vm) + __expf(v.z - vm) + __expf(v.w - vm);
#pragma unroll
        for (int o = 16; o; o >>= 1) se += __shfl_xor_sync(0xffffffffu, se, o);
        float l = vm + logf(se);
        if (lane < NL) {
            v.x -= l;
            v.y -= l;
            v.z -= l;
            v.w -= l;
            reinterpret_cast<float4*>(out)[(size_t)d * NL + cid] = v;
        }
    } else {
        if (lane < NL) {
            if (RELU) {
                v.x = fmaxf(v.x, 0.f);
                v.y = fmaxf(v.y, 0.f);
                v.z = fmaxf(v.z, 0.f);
                v.w = fmaxf(v.w, 0.f);
            }
            reinterpret_cast<float4*>(out)[(size_t)d * NL + cid] = v;
        }
    }
}

// ---------------- launch ----------------
extern "C" void kernel_launch(void* const* d_in, const int* in_sizes, int n_in,
                              void* d_out, int out_size) {
    (void)in_sizes;
    (void)n_in;
    (void)out_size;
    const float* x    = (const float*)d_in[0];
    const int*   ei   = (const int*)d_in[1];
    const float* W0   = (const float*)d_in[2];
    const float* att0 = (const float*)d_in[3];
    const float* W1   = (const float*)d_in[4];
    const float* att1 = (const float*)d_in[5];
    float* out = (float*)d_out;

    void *p;
    float *h0, *h1, *h2, *adst, *asrc;
    int *rowptr, *cursor, *colp, *bsum;
    cudaGetSymbolAddress(&p, g_h0);     h0 = (float*)p;
    cudaGetSymbolAddress(&p, g_h1);     h1 = (float*)p;
    cudaGetSymbolAddress(&p, g_h2);     h2 = (float*)p;
    cudaGetSymbolAddress(&p, g_adst);   adst = (float*)p;
    cudaGetSymbolAddress(&p, g_asrc);   asrc = (float*)p;
    cudaGetSymbolAddress(&p, g_rowptr); rowptr = (int*)p;
    cudaGetSymbolAddress(&p, g_cursor); cursor = (int*)p;
    cudaGetSymbolAddress(&p, g_col);    colp = (int*)p;
    cudaGetSymbolAddress(&p, g_bsum);   bsum = (int*)p;

    cudaFuncSetAttribute(gemm1_hist_kernel,
                         cudaFuncAttributeMaxDynamicSharedMemorySize, 98304);
    cudaFuncSetAttribute(gemm2_kernel,
                         cudaFuncAttributeMaxDynamicSharedMemorySize, 49152);

    const int TB = 256;
    int warp_blocks = (NN * 32 + TB - 1) / TB; // 12500

    // zero degree counters (async memset node; cheaper than a kernel launch)
    cudaMemsetAsync(cursor, 0, NN * sizeof(int));

    // Layer-1 GEMM fused with the (independent) degree histogram
    gemm1_hist_kernel<<<HB + GB1, TB, 98304>>>(x, W0, att0, h0, adst, asrc, ei, cursor);

    // CSR finalize
    scan1_kernel<<<NBLK, 1024>>>(cursor, rowptr, bsum);
    scan23_kernel<<<NBLK, 1024>>>(rowptr, bsum, cursor);
    scatter_kernel<<<(EE / 4 + TB - 1) / TB, TB>>>(ei, cursor, colp);

    // Layer 1 aggregation: 64ch, relu
    aggregate_kernel<64, true, false><<<warp_blocks, TB>>>(h0, adst, asrc, rowptr, colp, h1);

    // Layer 2: 64 -> 40, fused log_softmax
    gemm2_kernel<<<GB1, TB, 49152>>>(h1, W1, att1, h2, adst, asrc);
    aggregate_kernel<40, false, true><<<warp_blocks, TB>>>(h2, adst, asrc, rowptr, colp, out);
}

// round 5
// speedup vs baseline: 1.2098x; 1.1079x over previous
#include <cuda_runtime.h>
#include <cuda_bf16.h>
#include <cstdint>

#define NN 100000
#define EE 1600000
#define NBLK 98          // ceil(NN/1024)
#define GB1 782          // gemm1 blocks: ceil(NN/128)

// ---------------- scratch ----------------
__device__ __align__(16) float g_h0[NN * 64];
__device__ __align__(16) float g_h1[NN * 64];
__device__ __align__(16) float g_h2[NN * 40];
__device__ float g_adst[NN];
__device__ float g_asrc[NN];
__device__ int   g_rowptr[NN + 1];
__device__ int   g_cursor[NN];
__device__ int   g_col[EE];
__device__ int   g_bsum[128];

// ---------------- warp mma helper (sm_80+ baseline PTX; HMMA on Blackwell) ----------
__device__ __forceinline__ void mma16816(float* c, const uint32_t* a, const uint32_t* b) {
    asm volatile(
        "mma.sync.aligned.m16n8k16.row.col.f32.bf16.bf16.f32 "
        "{%0,%1,%2,%3}, {%4,%5,%6,%7}, {%8,%9}, {%0,%1,%2,%3};"
        : "+f"(c[0]), "+f"(c[1]), "+f"(c[2]), "+f"(c[3])
        : "r"(a[0]), "r"(a[1]), "r"(a[2]), "r"(a[3]), "r"(b[0]), "r"(b[1]));
}

__device__ __forceinline__ uint32_t pack_bf16_hi(float x, float y) {
    __nv_bfloat16 hx = __float2bfloat16_rn(x), hy = __float2bfloat16_rn(y);
    return (uint32_t)__bfloat16_as_ushort(hx) | ((uint32_t)__bfloat16_as_ushort(hy) << 16);
}
__device__ __forceinline__ uint32_t pack_bf16_lo(float x, float y) {
    __nv_bfloat16 hx = __float2bfloat16_rn(x), hy = __float2bfloat16_rn(y);
    __nv_bfloat16 lx = __float2bfloat16_rn(x - __bfloat162float(hx));
    __nv_bfloat16 ly = __float2bfloat16_rn(y - __bfloat162float(hy));
    return (uint32_t)__bfloat16_as_ushort(lx) | ((uint32_t)__bfloat16_as_ushort(ly) << 16);
}

// ---------------- layer-1 GEMM (warp mma, bf16 2-term split) + embedded hist --------
// Per CTA: D[128,64] = A[128,128] @ W[64,128]^T, 8 warps in 4(M)x2(N), 32x32 C per
// warp in registers. Split terms: AH*BH + AH*BL + AL*BH (lo*lo dropped, ~2^-18 rel).
// Smem rows padded to 272B: 4-bank rotation per row -> conflict-free 32-bit frag loads.
// Each CTA also histograms 2048 edges (RED atomics overlap the prologue).
#define SAS 272
#define SM_ATT 0
#define SM_PD  512
#define SM_PS  1024
#define SM_AHI 1536
#define SM_ALO (SM_AHI + 128 * SAS)
#define SM_BHI (SM_ALO + 128 * SAS)
#define SM_BLO (SM_BHI + 64 * SAS)
#define SM_TOT (SM_BLO + 64 * SAS)

__global__ void __launch_bounds__(256) gemm1_mma_kernel(
    const float* __restrict__ A, const float* __restrict__ W,
    const float* __restrict__ att, float* __restrict__ C,
    float* __restrict__ adst, float* __restrict__ asrc,
    const int* __restrict__ ei, int* __restrict__ deg) {
    extern __shared__ char ds[];
    int tid = threadIdx.x;
    int row0 = blockIdx.x * 128;

    // embedded degree histogram: 2048 edges per CTA (RED, no return -> no stall)
    {
        int t4 = blockIdx.x * 512 + tid * 2;
#pragma unroll
        for (int q = 0; q < 2; ++q) {
            if (t4 + q < EE / 4) {
                int4 d4 = reinterpret_cast<const int4*>(ei + EE)[t4 + q];
                atomicAdd(deg + d4.x, 1);
                atomicAdd(deg + d4.y, 1);
                atomicAdd(deg + d4.z, 1);
                atomicAdd(deg + d4.w, 1);
            }
        }
    }

    float* att_s = reinterpret_cast<float*>(ds + SM_ATT);
    float* spd = reinterpret_cast<float*>(ds + SM_PD);
    float* sps = reinterpret_cast<float*>(ds + SM_PS);
    if (tid < 128) {
        att_s[tid] = __ldg(att + tid);
        spd[tid] = 0.f;
        sps[tid] = 0.f;
    }

    // ---- A tile: 128x128 fp32 -> bf16 hi/lo into padded smem
    const float4* A4 = reinterpret_cast<const float4*>(A);
    for (int idx = tid; idx < 128 * 32; idx += 256) {
        int r = idx >> 5, c4 = idx & 31;
        float4 v = make_float4(0.f, 0.f, 0.f, 0.f);
        int gn = row0 + r;
        if (gn < NN) v = A4[gn * 32 + c4];
        uint2 hi, lo;
        hi.x = pack_bf16_hi(v.x, v.y);
        hi.y = pack_bf16_hi(v.z, v.w);
        lo.x = pack_bf16_lo(v.x, v.y);
        lo.y = pack_bf16_lo(v.z, v.w);
        int off = r * SAS + c4 * 8;
        *reinterpret_cast<uint2*>(ds + SM_AHI + off) = hi;
        *reinterpret_cast<uint2*>(ds + SM_ALO + off) = lo;
    }
    // ---- B tile: W 64x128 fp32 -> bf16 hi/lo
    const float4* W4 = reinterpret_cast<const float4*>(W);
    for (int idx = tid; idx < 64 * 32; idx += 256) {
        int r = idx >> 5, c4 = idx & 31;
        float4 v = W4[r * 32 + c4];
        uint2 hi, lo;
        hi.x = pack_bf16_hi(v.x, v.y);
        hi.y = pack_bf16_hi(v.z, v.w);
        lo.x = pack_bf16_lo(v.x, v.y);
        lo.y = pack_bf16_lo(v.z, v.w);
        int off = r * SAS + c4 * 8;
        *reinterpret_cast<uint2*>(ds + SM_BHI + off) = hi;
        *reinterpret_cast<uint2*>(ds + SM_BLO + off) = lo;
    }
    __syncthreads();

    int wid = tid >> 5;
    int lane = tid & 31;
    int wm = wid & 3;    // M group: rows wm*32..wm*32+31
    int wn = wid >> 2;   // N group: cols wn*32..wn*32+31
    int g = lane >> 2;   // 0..7
    int t = lane & 3;    // 0..3

    float c[2][4][4];
#pragma unroll
    for (int mt = 0; mt < 2; ++mt)
#pragma unroll
        for (int nt = 0; nt < 4; ++nt)
#pragma unroll
            for (int q = 0; q < 4; ++q) c[mt][nt][q] = 0.f;

    // per-thread smem byte offsets (row/k-invariant parts)
    int arow0 = (wm * 32 + g) * SAS + t * 4;         // mt=0 row g
    int brow0 = (wn * 32 + g) * SAS + t * 4;         // nt=0 n-row g

#pragma unroll
    for (int kk = 0; kk < 8; ++kk) {
        int kb = kk * 32;
        uint32_t aH[2][4], aL[2][4], bH[4][2], bL[4][2];
#pragma unroll
        for (int mt = 0; mt < 2; ++mt) {
            int base = arow0 + mt * 16 * SAS + kb;
            aH[mt][0] = *reinterpret_cast<const uint32_t*>(ds + SM_AHI + base);
            aH[mt][1] = *reinterpret_cast<const uint32_t*>(ds + SM_AHI + base + 8 * SAS);
            aH[mt][2] = *reinterpret_cast<const uint32_t*>(ds + SM_AHI + base + 16);
            aH[mt][3] = *reinterpret_cast<const uint32_t*>(ds + SM_AHI + base + 8 * SAS + 16);
            aL[mt][0] = *reinterpret_cast<const uint32_t*>(ds + SM_ALO + base);
            aL[mt][1] = *reinterpret_cast<const uint32_t*>(ds + SM_ALO + base + 8 * SAS);
            aL[mt][2] = *reinterpret_cast<const uint32_t*>(ds + SM_ALO + base + 16);
            aL[mt][3] = *reinterpret_cast<const uint32_t*>(ds + SM_ALO + base + 8 * SAS + 16);
        }
#pragma unroll
        for (int nt = 0; nt < 4; ++nt) {
            int base = brow0 + nt * 8 * SAS + kb;
            bH[nt][0] = *reinterpret_cast<const uint32_t*>(ds + SM_BHI + base);
            bH[nt][1] = *reinterpret_cast<const uint32_t*>(ds + SM_BHI + base + 16);
            bL[nt][0] = *reinterpret_cast<const uint32_t*>(ds + SM_BLO + base);
            bL[nt][1] = *reinterpret_cast<const uint32_t*>(ds + SM_BLO + base + 16);
        }
#pragma unroll
        for (int mt = 0; mt < 2; ++mt)
#pragma unroll
            for (int nt = 0; nt < 4; ++nt) {
                mma16816(c[mt][nt], aH[mt], bH[nt]);
                mma16816(c[mt][nt], aH[mt], bL[nt]);
                mma16816(c[mt][nt], aL[mt], bH[nt]);
            }
    }

    // ---- epilogue: store C + alpha dot partials (quad-reduce -> shared atomics)
#pragma unroll
    for (int mt = 0; mt < 2; ++mt) {
        int lr0 = wm * 32 + mt * 16 + g;   // local row of c0/c1
        int lr1 = lr0 + 8;                 // local row of c2/c3
        int gn0 = row0 + lr0, gn1 = row0 + lr1;
        float pd0 = 0.f, ps0 = 0.f, pd1 = 0.f, ps1 = 0.f;
#pragma unroll
        for (int nt = 0; nt < 4; ++nt) {
            int col = wn * 32 + nt * 8 + 2 * t;
            float c0 = c[mt][nt][0], c1 = c[mt][nt][1];
            float c2 = c[mt][nt][2], c3 = c[mt][nt][3];
            pd0 += c0 * att_s[col] + c1 * att_s[col + 1];
            ps0 += c0 * att_s[64 + col] + c1 * att_s[64 + col + 1];
            pd1 += c2 * att_s[col] + c3 * att_s[col + 1];
            ps1 += c2 * att_s[64 + col] + c3 * att_s[64 + col + 1];
            if (gn0 < NN)
                *reinterpret_cast<float2*>(C + (size_t)gn0 * 64 + col) = make_float2(c0, c1);
            if (gn1 < NN)
                *reinterpret_cast<float2*>(C + (size_t)gn1 * 64 + col) = make_float2(c2, c3);
        }
        // reduce across the 4 lanes of the quad (same rows)
#pragma unroll
        for (int o = 1; o <= 2; o <<= 1) {
            pd0 += __shfl_down_sync(0xffffffffu, pd0, o);
            ps0 += __shfl_down_sync(0xffffffffu, ps0, o);
            pd1 += __shfl_down_sync(0xffffffffu, pd1, o);
            ps1 += __shfl_down_sync(0xffffffffu, ps1, o);
        }
        if (t == 0) {
            atomicAdd(spd + lr0, pd0);
            atomicAdd(sps + lr0, ps0);
            atomicAdd(spd + lr1, pd1);
            atomicAdd(sps + lr1, ps1);
        }
    }
    __syncthreads();
    if (tid < 128) {
        int gn = row0 + tid;
        if (gn < NN) {
            adst[gn] = spd[tid];
            asrc[gn] = sps[tid];
        }
    }
}

// ---------------- SIMT GEMM body for layer 2 (64 -> 40) + alpha epilogue ------------
template <int K, int CO>
__device__ __forceinline__ void gemm_body(int bid, const float* __restrict__ A,
                                          const float* __restrict__ W,
                                          const float* __restrict__ att,
                                          float* __restrict__ C,
                                          float* __restrict__ adst,
                                          float* __restrict__ asrc) {
    constexpr int K4 = K / 4;
    extern __shared__ float4 smem[];
    float4* xs = smem;
    float4* ws = smem + 128 * K4;

    int tid = threadIdx.x;
    int row0 = bid * 128;

    for (int idx = tid; idx < 128 * K4; idx += 256) {
        int n = idx / K4, k4 = idx - n * K4;
        float4 v = make_float4(0.f, 0.f, 0.f, 0.f);
        int gn = row0 + n;
        if (gn < NN) v = reinterpret_cast<const float4*>(A)[gn * K4 + k4];
        xs[n * K4 + ((k4 + (n >> 2)) & (K4 - 1))] = v;
    }
    for (int idx = tid; idx < 64 * K4; idx += 256) {
        int cix = idx / K4, k4 = idx - cix * K4;
        float4 v = make_float4(0.f, 0.f, 0.f, 0.f);
        if (cix < CO) v = reinterpret_cast<const float4*>(W)[cix * K4 + k4];
        ws[cix * K4 + ((k4 + (cix >> 3)) & (K4 - 1))] = v;
    }
    __syncthreads();

    int tc = tid & 7;
    int tn = tid >> 3;

    float acc[4][8];
#pragma unroll
    for (int i = 0; i < 4; ++i)
#pragma unroll
        for (int j = 0; j < 8; ++j) acc[i][j] = 0.f;

#pragma unroll 4
    for (int k4 = 0; k4 < K4; ++k4) {
        float4 a[4], b[8];
        int ka = (k4 + tn) & (K4 - 1);
        int kb = (k4 + tc) & (K4 - 1);
#pragma unroll
        for (int i = 0; i < 4; ++i) a[i] = xs[(tn * 4 + i) * K4 + ka];
#pragma unroll
        for (int j = 0; j < 8; ++j) b[j] = ws[(tc * 8 + j) * K4 + kb];
#pragma unroll
        for (int i = 0; i < 4; ++i)
#pragma unroll
            for (int j = 0; j < 8; ++j) {
                acc[i][j] += a[i].x * b[j].x;
                acc[i][j] += a[i].y * b[j].y;
                acc[i][j] += a[i].z * b[j].z;
                acc[i][j] += a[i].w * b[j].w;
            }
    }

#pragma unroll
    for (int i = 0; i < 4; ++i) {
        int gn = row0 + tn * 4 + i;
        if (gn < NN) {
#pragma unroll
            for (int j = 0; j < 8; ++j) {
                int cix = tc * 8 + j;
                if (cix < CO) C[gn * CO + cix] = acc[i][j];
            }
        }
    }

    float ai[8], aj[8];
#pragma unroll
    for (int j = 0; j < 8; ++j) {
        int cix = tc * 8 + j;
        ai[j] = (cix < CO) ? __ldg(att + cix) : 0.f;
        aj[j] = (cix < CO) ? __ldg(att + CO + cix) : 0.f;
    }
    float pd[4], ps[4];
#pragma unroll
    for (int i = 0; i < 4; ++i) {
        pd[i] = 0.f;
        ps[i] = 0.f;
#pragma unroll
        for (int j = 0; j < 8; ++j) {
            pd[i] += acc[i][j] * ai[j];
            ps[i] += acc[i][j] * aj[j];
        }
    }
#pragma unroll
    for (int o = 4; o; o >>= 1) {
#pragma unroll
        for (int i = 0; i < 4; ++i) {
            pd[i] += __shfl_xor_sync(0xffffffffu, pd[i], o);
            ps[i] += __shfl_xor_sync(0xffffffffu, ps[i], o);
        }
    }
    if (tc == 0) {
#pragma unroll
        for (int i = 0; i < 4; ++i) {
            int gn = row0 + tn * 4 + i;
            if (gn < NN) {
                adst[gn] = pd[i];
                asrc[gn] = ps[i];
            }
        }
    }
}

__global__ void __launch_bounds__(256) gemm2_kernel(const float* __restrict__ A,
                                                    const float* __restrict__ W,
                                                    const float* __restrict__ att,
                                                    float* __restrict__ C,
                                                    float* __restrict__ adst,
                                                    float* __restrict__ asrc) {
    gemm_body<64, 40>(blockIdx.x, A, W, att, C, adst, asrc);
}

// ---------------- CSR build ----------------
__global__ void scan1_kernel(const int* __restrict__ deg, int* __restrict__ rowp,
                             int* __restrict__ bsum) {
    __shared__ int sh[1024];
    int tid = threadIdx.x;
    int i = blockIdx.x * 1024 + tid;
    int v = (i < NN) ? deg[i] : 0;
    sh[tid] = v;
    __syncthreads();
    for (int off = 1; off < 1024; off <<= 1) {
        int t = (tid >= off) ? sh[tid - off] : 0;
        __syncthreads();
        sh[tid] += t;
        __syncthreads();
    }
    if (i < NN) rowp[i] = sh[tid] - v;
    if (tid == 1023) bsum[blockIdx.x] = sh[1023];
}

__global__ void scan23_kernel(int* __restrict__ rowp, const int* __restrict__ bsum,
                              int* __restrict__ cursor) {
    __shared__ int soff;
    int tid = threadIdx.x;
    if (tid == 0) soff = 0;
    __syncthreads();
    if (tid < blockIdx.x) atomicAdd(&soff, bsum[tid]);
    __syncthreads();
    int off = soff;
    int i = blockIdx.x * 1024 + tid;
    if (i < NN) {
        int r = rowp[i] + off;
        rowp[i] = r;
        cursor[i] = r;
    }
    if (i == 0) rowp[NN] = EE;
}

__global__ void scatter_kernel(const int* __restrict__ ei, int* __restrict__ cursor,
                               int* __restrict__ col) {
    int t = blockIdx.x * blockDim.x + threadIdx.x;
    if (t < EE / 4) {
        int4 s4 = reinterpret_cast<const int4*>(ei)[t];
        int4 d4 = reinterpret_cast<const int4*>(ei + EE)[t];
        int p;
        p = atomicAdd(cursor + d4.x, 1); col[p] = s4.x;
        p = atomicAdd(cursor + d4.y, 1); col[p] = s4.y;
        p = atomicAdd(cursor + d4.z, 1); col[p] = s4.z;
        p = atomicAdd(cursor + d4.w, 1); col[p] = s4.w;
    }
}

// ---------------- fused segment softmax + aggregation (warp per dst) ----------------
__device__ __forceinline__ float lrelu(float x) { return x < 0.f ? 0.2f * x : x; }

template <int CH, bool RELU, bool LSM>
__global__ void aggregate_kernel(const float* __restrict__ h, const float* __restrict__ adst,
                                 const float* __restrict__ asrc, const int* __restrict__ rowp,
                                 const int* __restrict__ col, float* __restrict__ out) {
    constexpr int NL = CH / 4;
    constexpr int NS = 32 / NL;

    int d = (blockIdx.x * blockDim.x + threadIdx.x) >> 5;
    int lane = threadIdx.x & 31;
    if (d >= NN) return;

    int rs = __ldg(rowp + d), re = __ldg(rowp + d + 1);
    float ad = adst[d];

    int group = lane / NL;
    int cid = lane - group * NL;
    bool act = group < NS;

    const float4* __restrict__ h4 = reinterpret_cast<const float4*>(h);

    float4 acc = make_float4(0.f, 0.f, 0.f, 0.f);
    float psum = 0.f;

    for (int base = rs; base < re; base += 32) {
        int i = base + lane;
        int s = 0;
        float e = 0.f;
        if (i < re) {
            s = col[i];
            e = __expf(lrelu(ad + __ldg(asrc + s)));
        }
        psum += e;
        int cnt = min(32, re - base);
        for (int j = 0; j < cnt; j += NS) {
            int pj = j + group;
            float ej = __shfl_sync(0xffffffffu, e, pj & 31);
            int sj = __shfl_sync(0xffffffffu, s, pj & 31);
            if (!act || pj >= cnt) ej = 0.f;
            float4 hv = h4[(size_t)sj * NL + cid];
            acc.x += ej * hv.x;
            acc.y += ej * hv.y;
            acc.z += ej * hv.z;
            acc.w += ej * hv.w;
        }
    }

#pragma unroll
    for (int o = 16; o; o >>= 1) psum += __shfl_xor_sync(0xffffffffu, psum, o);

#pragma unroll
    for (int gq = 1; gq < NS; ++gq) {
        int srcl = cid + gq * NL;
        float tx = __shfl_sync(0xffffffffu, acc.x, srcl & 31);
        float ty = __shfl_sync(0xffffffffu, acc.y, srcl & 31);
        float tz = __shfl_sync(0xffffffffu, acc.z, srcl & 31);
        float tw = __shfl_sync(0xffffffffu, acc.w, srcl & 31);
        if (lane < NL) {
            acc.x += tx;
            acc.y += ty;
            acc.z += tz;
            acc.w += tw;
        }
    }

    float es = __expf(lrelu(ad + __ldg(asrc + d)));
    psum += es;

    float4 v = make_float4(0.f, 0.f, 0.f, 0.f);
    if (lane < NL) {
        float4 hv = h4[(size_t)d * NL + cid];
        float inv = 1.0f / psum;
        v.x = (acc.x + es * hv.x) * inv;
        v.y = (acc.y + es * hv.y) * inv;
        v.z = (acc.z + es * hv.z) * inv;
        v.w = (acc.w + es * hv.w) * inv;
    }

    if (LSM) {
        float vm = -1e30f;
        if (lane < NL) vm = fmaxf(fmaxf(v.x, v.y), fmaxf(v.z, v.w));
#pragma unroll
        for (int o = 16; o; o >>= 1) vm = fmaxf(vm, __shfl_xor_sync(0xffffffffu, vm, o));
        float se = 0.f;
        if (lane < NL)
            se = __expf(v.x - vm) + __expf(v.y - vm) + __expf(v.z - vm) + __expf(v.w - vm);
#pragma unroll
        for (int o = 16; o; o >>= 1) se += __shfl_xor_sync(0xffffffffu, se, o);
        float l = vm + logf(se);
        if (lane < NL) {
            v.x -= l;
            v.y -= l;
            v.z -= l;
            v.w -= l;
            reinterpret_cast<float4*>(out)[(size_t)d * NL + cid] = v;
        }
    } else {
        if (lane < NL) {
            if (RELU) {
                v.x = fmaxf(v.x, 0.f);
                v.y = fmaxf(v.y, 0.f);
                v.z = fmaxf(v.z, 0.f);
                v.w = fmaxf(v.w, 0.f);
            }
            reinterpret_cast<float4*>(out)[(size_t)d * NL + cid] = v;
        }
    }
}

// ---------------- launch ----------------
extern "C" void kernel_launch(void* const* d_in, const int* in_sizes, int n_in,
                              void* d_out, int out_size) {
    (void)in_sizes;
    (void)n_in;
    (void)out_size;
    const float* x    = (const float*)d_in[0];
    const int*   ei   = (const int*)d_in[1];
    const float* W0   = (const float*)d_in[2];
    const float* att0 = (const float*)d_in[3];
    const float* W1   = (const float*)d_in[4];
    const float* att1 = (const float*)d_in[5];
    float* out = (float*)d_out;

    void *p;
    float *h0, *h1, *h2, *adst, *asrc;
    int *rowptr, *cursor, *colp, *bsum;
    cudaGetSymbolAddress(&p, g_h0);     h0 = (float*)p;
    cudaGetSymbolAddress(&p, g_h1);     h1 = (float*)p;
    cudaGetSymbolAddress(&p, g_h2);     h2 = (float*)p;
    cudaGetSymbolAddress(&p, g_adst);   adst = (float*)p;
    cudaGetSymbolAddress(&p, g_asrc);   asrc = (float*)p;
    cudaGetSymbolAddress(&p, g_rowptr); rowptr = (int*)p;
    cudaGetSymbolAddress(&p, g_cursor); cursor = (int*)p;
    cudaGetSymbolAddress(&p, g_col);    colp = (int*)p;
    cudaGetSymbolAddress(&p, g_bsum);   bsum = (int*)p;

    cudaFuncSetAttribute(gemm1_mma_kernel,
                         cudaFuncAttributeMaxDynamicSharedMemorySize, SM_TOT);
    cudaFuncSetAttribute(gemm2_kernel,
                         cudaFuncAttributeMaxDynamicSharedMemorySize, 49152);

    const int TB = 256;
    int warp_blocks = (NN * 32 + TB - 1) / TB; // 12500

    cudaMemsetAsync(cursor, 0, NN * sizeof(int));

    // Layer-1 GEMM (warp mma.sync) with embedded degree histogram
    gemm1_mma_kernel<<<GB1, TB, SM_TOT>>>(x, W0, att0, h0, adst, asrc, ei, cursor);

    // CSR finalize
    scan1_kernel<<<NBLK, 1024>>>(cursor, rowptr, bsum);
    scan23_kernel<<<NBLK, 1024>>>(rowptr, bsum, cursor);
    scatter_kernel<<<(EE / 4 + TB - 1) / TB, TB>>>(ei, cursor, colp);

    // Layer 1 aggregation: 64ch, relu
    aggregate_kernel<64, true, false><<<warp_blocks, TB>>>(h0, adst, asrc, rowptr, colp, h1);

    // Layer 2: 64 -> 40, fused log_softmax
    gemm2_kernel<<<GB1, TB, 49152>>>(h1, W1, att1, h2, adst, asrc);
    aggregate_kernel<40, false, true><<<warp_blocks, TB>>>(h2, adst, asrc, rowptr, colp, out);
}

// round 6
// speedup vs baseline: 1.3319x; 1.1009x over previous
#include <cuda_runtime.h>
#include <cuda_bf16.h>
#include <cstdint>

#define NN 100000
#define EE 1600000
#define NBLK 98          // ceil(NN/1024)
#define GB1 782          // gemm blocks: ceil(NN/128)

// ---------------- scratch ----------------
__device__ __align__(16) float g_h0[NN * 64];
__device__ __align__(16) float g_h1[NN * 64];
__device__ __align__(16) float g_h2[NN * 40];
__device__ float g_adst[NN];
__device__ float g_asrc[NN];
__device__ int   g_rowptr[NN + 1];
__device__ int   g_cursor[NN];
__device__ int   g_col[EE];
__device__ int   g_bsum[128];

// ---------------- warp mma helper (sm_80+ baseline PTX; HMMA on Blackwell) ----------
__device__ __forceinline__ void mma16816(float* c, const uint32_t* a, const uint32_t* b) {
    asm volatile(
        "mma.sync.aligned.m16n8k16.row.col.f32.bf16.bf16.f32 "
        "{%0,%1,%2,%3}, {%4,%5,%6,%7}, {%8,%9}, {%0,%1,%2,%3};"
        : "+f"(c[0]), "+f"(c[1]), "+f"(c[2]), "+f"(c[3])
        : "r"(a[0]), "r"(a[1]), "r"(a[2]), "r"(a[3]), "r"(b[0]), "r"(b[1]));
}

__device__ __forceinline__ uint32_t pack_bf16_hi(float x, float y) {
    __nv_bfloat16 hx = __float2bfloat16_rn(x), hy = __float2bfloat16_rn(y);
    return (uint32_t)__bfloat16_as_ushort(hx) | ((uint32_t)__bfloat16_as_ushort(hy) << 16);
}
__device__ __forceinline__ uint32_t pack_bf16_lo(float x, float y) {
    __nv_bfloat16 hx = __float2bfloat16_rn(x), hy = __float2bfloat16_rn(y);
    __nv_bfloat16 lx = __float2bfloat16_rn(x - __bfloat162float(hx));
    __nv_bfloat16 ly = __float2bfloat16_rn(y - __bfloat162float(hy));
    return (uint32_t)__bfloat16_as_ushort(lx) | ((uint32_t)__bfloat16_as_ushort(ly) << 16);
}

// ---------------- layer-1 GEMM (warp mma, bf16 2-term split) + embedded hist --------
#define SAS 272
#define SM_ATT 0
#define SM_PD  512
#define SM_PS  1024
#define SM_AHI 1536
#define SM_ALO (SM_AHI + 128 * SAS)
#define SM_BHI (SM_ALO + 128 * SAS)
#define SM_BLO (SM_BHI + 64 * SAS)
#define SM_TOT (SM_BLO + 64 * SAS)

__global__ void __launch_bounds__(256) gemm1_mma_kernel(
    const float* __restrict__ A, const float* __restrict__ W,
    const float* __restrict__ att, float* __restrict__ C,
    float* __restrict__ adst, float* __restrict__ asrc,
    const int* __restrict__ ei, int* __restrict__ deg) {
    extern __shared__ char ds[];
    int tid = threadIdx.x;
    int row0 = blockIdx.x * 128;

    // embedded degree histogram: 2048 edges per CTA (fire-and-forget RED)
    {
        int t4 = blockIdx.x * 512 + tid * 2;
#pragma unroll
        for (int q = 0; q < 2; ++q) {
            if (t4 + q < EE / 4) {
                int4 d4 = reinterpret_cast<const int4*>(ei + EE)[t4 + q];
                atomicAdd(deg + d4.x, 1);
                atomicAdd(deg + d4.y, 1);
                atomicAdd(deg + d4.z, 1);
                atomicAdd(deg + d4.w, 1);
            }
        }
    }

    float* att_s = reinterpret_cast<float*>(ds + SM_ATT);
    float* spd = reinterpret_cast<float*>(ds + SM_PD);
    float* sps = reinterpret_cast<float*>(ds + SM_PS);
    if (tid < 128) {
        att_s[tid] = __ldg(att + tid);
        spd[tid] = 0.f;
        sps[tid] = 0.f;
    }

    const float4* A4 = reinterpret_cast<const float4*>(A);
    for (int idx = tid; idx < 128 * 32; idx += 256) {
        int r = idx >> 5, c4 = idx & 31;
        float4 v = make_float4(0.f, 0.f, 0.f, 0.f);
        int gn = row0 + r;
        if (gn < NN) v = A4[gn * 32 + c4];
        uint2 hi, lo;
        hi.x = pack_bf16_hi(v.x, v.y);
        hi.y = pack_bf16_hi(v.z, v.w);
        lo.x = pack_bf16_lo(v.x, v.y);
        lo.y = pack_bf16_lo(v.z, v.w);
        int off = r * SAS + c4 * 8;
        *reinterpret_cast<uint2*>(ds + SM_AHI + off) = hi;
        *reinterpret_cast<uint2*>(ds + SM_ALO + off) = lo;
    }
    const float4* W4 = reinterpret_cast<const float4*>(W);
    for (int idx = tid; idx < 64 * 32; idx += 256) {
        int r = idx >> 5, c4 = idx & 31;
        float4 v = W4[r * 32 + c4];
        uint2 hi, lo;
        hi.x = pack_bf16_hi(v.x, v.y);
        hi.y = pack_bf16_hi(v.z, v.w);
        lo.x = pack_bf16_lo(v.x, v.y);
        lo.y = pack_bf16_lo(v.z, v.w);
        int off = r * SAS + c4 * 8;
        *reinterpret_cast<uint2*>(ds + SM_BHI + off) = hi;
        *reinterpret_cast<uint2*>(ds + SM_BLO + off) = lo;
    }
    __syncthreads();

    int wid = tid >> 5;
    int lane = tid & 31;
    int wm = wid & 3;
    int wn = wid >> 2;
    int g = lane >> 2;
    int t = lane & 3;

    float c[2][4][4];
#pragma unroll
    for (int mt = 0; mt < 2; ++mt)
#pragma unroll
        for (int nt = 0; nt < 4; ++nt)
#pragma unroll
            for (int q = 0; q < 4; ++q) c[mt][nt][q] = 0.f;

    int arow0 = (wm * 32 + g) * SAS + t * 4;
    int brow0 = (wn * 32 + g) * SAS + t * 4;

#pragma unroll
    for (int kk = 0; kk < 8; ++kk) {
        int kb = kk * 32;
        uint32_t aH[2][4], aL[2][4], bH[4][2], bL[4][2];
#pragma unroll
        for (int mt = 0; mt < 2; ++mt) {
            int base = arow0 + mt * 16 * SAS + kb;
            aH[mt][0] = *reinterpret_cast<const uint32_t*>(ds + SM_AHI + base);
            aH[mt][1] = *reinterpret_cast<const uint32_t*>(ds + SM_AHI + base + 8 * SAS);
            aH[mt][2] = *reinterpret_cast<const uint32_t*>(ds + SM_AHI + base + 16);
            aH[mt][3] = *reinterpret_cast<const uint32_t*>(ds + SM_AHI + base + 8 * SAS + 16);
            aL[mt][0] = *reinterpret_cast<const uint32_t*>(ds + SM_ALO + base);
            aL[mt][1] = *reinterpret_cast<const uint32_t*>(ds + SM_ALO + base + 8 * SAS);
            aL[mt][2] = *reinterpret_cast<const uint32_t*>(ds + SM_ALO + base + 16);
            aL[mt][3] = *reinterpret_cast<const uint32_t*>(ds + SM_ALO + base + 8 * SAS + 16);
        }
#pragma unroll
        for (int nt = 0; nt < 4; ++nt) {
            int base = brow0 + nt * 8 * SAS + kb;
            bH[nt][0] = *reinterpret_cast<const uint32_t*>(ds + SM_BHI + base);
            bH[nt][1] = *reinterpret_cast<const uint32_t*>(ds + SM_BHI + base + 16);
            bL[nt][0] = *reinterpret_cast<const uint32_t*>(ds + SM_BLO + base);
            bL[nt][1] = *reinterpret_cast<const uint32_t*>(ds + SM_BLO + base + 16);
        }
#pragma unroll
        for (int mt = 0; mt < 2; ++mt)
#pragma unroll
            for (int nt = 0; nt < 4; ++nt) {
                mma16816(c[mt][nt], aH[mt], bH[nt]);
                mma16816(c[mt][nt], aH[mt], bL[nt]);
                mma16816(c[mt][nt], aL[mt], bH[nt]);
            }
    }

#pragma unroll
    for (int mt = 0; mt < 2; ++mt) {
        int lr0 = wm * 32 + mt * 16 + g;
        int lr1 = lr0 + 8;
        int gn0 = row0 + lr0, gn1 = row0 + lr1;
        float pd0 = 0.f, ps0 = 0.f, pd1 = 0.f, ps1 = 0.f;
#pragma unroll
        for (int nt = 0; nt < 4; ++nt) {
            int col = wn * 32 + nt * 8 + 2 * t;
            float c0 = c[mt][nt][0], c1 = c[mt][nt][1];
            float c2 = c[mt][nt][2], c3 = c[mt][nt][3];
            pd0 += c0 * att_s[col] + c1 * att_s[col + 1];
            ps0 += c0 * att_s[64 + col] + c1 * att_s[64 + col + 1];
            pd1 += c2 * att_s[col] + c3 * att_s[col + 1];
            ps1 += c2 * att_s[64 + col] + c3 * att_s[64 + col + 1];
            if (gn0 < NN)
                *reinterpret_cast<float2*>(C + (size_t)gn0 * 64 + col) = make_float2(c0, c1);
            if (gn1 < NN)
                *reinterpret_cast<float2*>(C + (size_t)gn1 * 64 + col) = make_float2(c2, c3);
        }
#pragma unroll
        for (int o = 1; o <= 2; o <<= 1) {
            pd0 += __shfl_down_sync(0xffffffffu, pd0, o);
            ps0 += __shfl_down_sync(0xffffffffu, ps0, o);
            pd1 += __shfl_down_sync(0xffffffffu, pd1, o);
            ps1 += __shfl_down_sync(0xffffffffu, ps1, o);
        }
        if (t == 0) {
            atomicAdd(spd + lr0, pd0);
            atomicAdd(sps + lr0, ps0);
            atomicAdd(spd + lr1, pd1);
            atomicAdd(sps + lr1, ps1);
        }
    }
    __syncthreads();
    if (tid < 128) {
        int gn = row0 + tid;
        if (gn < NN) {
            adst[gn] = spd[tid];
            asrc[gn] = sps[tid];
        }
    }
}

// ---------------- layer-2 GEMM (warp mma, bf16 2-term split, M=128 N=40 K=64) --------
// 8 warps all along M (16 rows each); each warp covers all 40 output cols via 5 n-tiles.
// Each output row owned by exactly one warp -> alpha dots need only a quad reduce.
#define S2AS 144
#define S2_ATT 0
#define S2_AHI 512
#define S2_ALO (S2_AHI + 128 * S2AS)
#define S2_BHI (S2_ALO + 128 * S2AS)
#define S2_BLO (S2_BHI + 40 * S2AS)
#define S2_TOT (S2_BLO + 40 * S2AS)

__global__ void __launch_bounds__(256) gemm2_mma_kernel(
    const float* __restrict__ A, const float* __restrict__ W,
    const float* __restrict__ att, float* __restrict__ C,
    float* __restrict__ adst, float* __restrict__ asrc) {
    extern __shared__ char ds[];
    int tid = threadIdx.x;
    int row0 = blockIdx.x * 128;

    float* att_s = reinterpret_cast<float*>(ds + S2_ATT);
    if (tid < 80) att_s[tid] = __ldg(att + tid);

    const float4* A4 = reinterpret_cast<const float4*>(A);
    for (int idx = tid; idx < 128 * 16; idx += 256) {
        int r = idx >> 4, c4 = idx & 15;
        float4 v = make_float4(0.f, 0.f, 0.f, 0.f);
        int gn = row0 + r;
        if (gn < NN) v = A4[gn * 16 + c4];
        uint2 hi, lo;
        hi.x = pack_bf16_hi(v.x, v.y);
        hi.y = pack_bf16_hi(v.z, v.w);
        lo.x = pack_bf16_lo(v.x, v.y);
        lo.y = pack_bf16_lo(v.z, v.w);
        int off = r * S2AS + c4 * 8;
        *reinterpret_cast<uint2*>(ds + S2_AHI + off) = hi;
        *reinterpret_cast<uint2*>(ds + S2_ALO + off) = lo;
    }
    const float4* W4 = reinterpret_cast<const float4*>(W);
    for (int idx = tid; idx < 40 * 16; idx += 256) {
        int r = idx >> 4, c4 = idx & 15;
        float4 v = W4[r * 16 + c4];
        uint2 hi, lo;
        hi.x = pack_bf16_hi(v.x, v.y);
        hi.y = pack_bf16_hi(v.z, v.w);
        lo.x = pack_bf16_lo(v.x, v.y);
        lo.y = pack_bf16_lo(v.z, v.w);
        int off = r * S2AS + c4 * 8;
        *reinterpret_cast<uint2*>(ds + S2_BHI + off) = hi;
        *reinterpret_cast<uint2*>(ds + S2_BLO + off) = lo;
    }
    __syncthreads();

    int wid = tid >> 5;
    int lane = tid & 31;
    int g = lane >> 2;
    int t = lane & 3;

    float c[5][4];
#pragma unroll
    for (int nt = 0; nt < 5; ++nt)
#pragma unroll
        for (int q = 0; q < 4; ++q) c[nt][q] = 0.f;

    int arow = (wid * 16 + g) * S2AS + t * 4;
    int brow = g * S2AS + t * 4;

#pragma unroll
    for (int kk = 0; kk < 4; ++kk) {
        int kb = kk * 32;
        uint32_t aH[4], aL[4], bH[5][2], bL[5][2];
        int base = arow + kb;
        aH[0] = *reinterpret_cast<const uint32_t*>(ds + S2_AHI + base);
        aH[1] = *reinterpret_cast<const uint32_t*>(ds + S2_AHI + base + 8 * S2AS);
        aH[2] = *reinterpret_cast<const uint32_t*>(ds + S2_AHI + base + 16);
        aH[3] = *reinterpret_cast<const uint32_t*>(ds + S2_AHI + base + 8 * S2AS + 16);
        aL[0] = *reinterpret_cast<const uint32_t*>(ds + S2_ALO + base);
        aL[1] = *reinterpret_cast<const uint32_t*>(ds + S2_ALO + base + 8 * S2AS);
        aL[2] = *reinterpret_cast<const uint32_t*>(ds + S2_ALO + base + 16);
        aL[3] = *reinterpret_cast<const uint32_t*>(ds + S2_ALO + base + 8 * S2AS + 16);
#pragma unroll
        for (int nt = 0; nt < 5; ++nt) {
            int bb = brow + nt * 8 * S2AS + kb;
            bH[nt][0] = *reinterpret_cast<const uint32_t*>(ds + S2_BHI + bb);
            bH[nt][1] = *reinterpret_cast<const uint32_t*>(ds + S2_BHI + bb + 16);
            bL[nt][0] = *reinterpret_cast<const uint32_t*>(ds + S2_BLO + bb);
            bL[nt][1] = *reinterpret_cast<const uint32_t*>(ds + S2_BLO + bb + 16);
        }
#pragma unroll
        for (int nt = 0; nt < 5; ++nt) {
            mma16816(c[nt], aH, bH[nt]);
            mma16816(c[nt], aH, bL[nt]);
            mma16816(c[nt], aL, bH[nt]);
        }
    }

    // epilogue: rows r0 = row0 + wid*16 + g (c0,c1) and r1 = r0+8 (c2,c3)
    int lr0 = wid * 16 + g, lr1 = lr0 + 8;
    int gn0 = row0 + lr0, gn1 = row0 + lr1;
    float pd0 = 0.f, ps0 = 0.f, pd1 = 0.f, ps1 = 0.f;
#pragma unroll
    for (int nt = 0; nt < 5; ++nt) {
        int col = nt * 8 + 2 * t;
        float c0 = c[nt][0], c1 = c[nt][1], c2 = c[nt][2], c3 = c[nt][3];
        pd0 += c0 * att_s[col] + c1 * att_s[col + 1];
        ps0 += c0 * att_s[40 + col] + c1 * att_s[40 + col + 1];
        pd1 += c2 * att_s[col] + c3 * att_s[col + 1];
        ps1 += c2 * att_s[40 + col] + c3 * att_s[40 + col + 1];
        if (gn0 < NN)
            *reinterpret_cast<float2*>(C + (size_t)gn0 * 40 + col) = make_float2(c0, c1);
        if (gn1 < NN)
            *reinterpret_cast<float2*>(C + (size_t)gn1 * 40 + col) = make_float2(c2, c3);
    }
#pragma unroll
    for (int o = 1; o <= 2; o <<= 1) {
        pd0 += __shfl_down_sync(0xffffffffu, pd0, o);
        ps0 += __shfl_down_sync(0xffffffffu, ps0, o);
        pd1 += __shfl_down_sync(0xffffffffu, pd1, o);
        ps1 += __shfl_down_sync(0xffffffffu, ps1, o);
    }
    if (t == 0) {
        if (gn0 < NN) {
            adst[gn0] = pd0;
            asrc[gn0] = ps0;
        }
        if (gn1 < NN) {
            adst[gn1] = pd1;
            asrc[gn1] = ps1;
        }
    }
}

// ---------------- CSR build: fused scan with decoupled lookback ----------------
// All 98 blocks are co-resident (one wave), so spinning on predecessors' published
// block sums is deadlock-free. Value+flag share one 32-bit word (sums < 2^24).
#define SCAN_FLAG 0x40000000

__global__ void __launch_bounds__(1024) scan_fused_kernel(
    const int* __restrict__ deg, int* __restrict__ rowp, int* __restrict__ cursor,
    int* __restrict__ partial) {
    __shared__ int wsum[32];
    __shared__ int s_off;
    int tid = threadIdx.x, b = blockIdx.x;
    int lane = tid & 31, w = tid >> 5;
    int i = b * 1024 + tid;
    int v = (i < NN) ? deg[i] : 0;

    // warp inclusive scan
    int x = v;
#pragma unroll
    for (int o = 1; o < 32; o <<= 1) {
        int y = __shfl_up_sync(0xffffffffu, x, o);
        if (lane >= o) x += y;
    }
    if (lane == 31) wsum[w] = x;
    __syncthreads();
    if (w == 0) {
        int s = wsum[lane];
#pragma unroll
        for (int o = 1; o < 32; o <<= 1) {
            int y = __shfl_up_sync(0xffffffffu, s, o);
            if (lane >= o) s += y;
        }
        wsum[lane] = s;
        if (lane == 31) {
            // publish block total (single-word value+flag: no fence needed)
            atomicExch(partial + b, s | SCAN_FLAG);
        }
        // lookback: sum all predecessor block totals
        int acc = 0;
        for (int j = lane; j < b; j += 32) {
            int p;
            do {
                p = *((volatile int*)(partial + j));
            } while (!(p & SCAN_FLAG));
            acc += p & (SCAN_FLAG - 1);
        }
#pragma unroll
        for (int o = 16; o; o >>= 1) acc += __shfl_xor_sync(0xffffffffu, acc, o);
        if (lane == 0) s_off = acc;
    }
    __syncthreads();
    int excl = ((w == 0) ? 0 : wsum[w - 1]) + x - v + s_off;
    if (i < NN) {
        rowp[i] = excl;
        cursor[i] = excl;
    }
    if (i == 0) rowp[NN] = EE;
}

__global__ void scatter_kernel(const int* __restrict__ ei, int* __restrict__ cursor,
                               int* __restrict__ col) {
    int t = blockIdx.x * blockDim.x + threadIdx.x;
    if (t < EE / 8) {
        const int4* S4 = reinterpret_cast<const int4*>(ei);
        const int4* D4 = reinterpret_cast<const int4*>(ei + EE);
        int4 sa = S4[2 * t], sb = S4[2 * t + 1];
        int4 da = D4[2 * t], db = D4[2 * t + 1];
        int p;
        p = atomicAdd(cursor + da.x, 1); col[p] = sa.x;
        p = atomicAdd(cursor + da.y, 1); col[p] = sa.y;
        p = atomicAdd(cursor + da.z, 1); col[p] = sa.z;
        p = atomicAdd(cursor + da.w, 1); col[p] = sa.w;
        p = atomicAdd(cursor + db.x, 1); col[p] = sb.x;
        p = atomicAdd(cursor + db.y, 1); col[p] = sb.y;
        p = atomicAdd(cursor + db.z, 1); col[p] = sb.z;
        p = atomicAdd(cursor + db.w, 1); col[p] = sb.w;
    }
}

// ---------------- fused segment softmax + aggregation (warp per dst) ----------------
__device__ __forceinline__ float lrelu(float x) { return x < 0.f ? 0.2f * x : x; }

template <int CH, bool RELU, bool LSM>
__global__ void aggregate_kernel(const float* __restrict__ h, const float* __restrict__ adst,
                                 const float* __restrict__ asrc, const int* __restrict__ rowp,
                                 const int* __restrict__ col, float* __restrict__ out) {
    constexpr int NL = CH / 4;
    constexpr int NS = 32 / NL;

    int d = (blockIdx.x * blockDim.x + threadIdx.x) >> 5;
    int lane = threadIdx.x & 31;
    if (d >= NN) return;

    int rs = __ldg(rowp + d), re = __ldg(rowp + d + 1);
    float ad = adst[d];

    int group = lane / NL;
    int cid = lane - group * NL;
    bool act = group < NS;

    const float4* __restrict__ h4 = reinterpret_cast<const float4*>(h);

    float4 acc = make_float4(0.f, 0.f, 0.f, 0.f);
    float psum = 0.f;

    for (int base = rs; base < re; base += 32) {
        int i = base + lane;
        int s = 0;
        float e = 0.f;
        if (i < re) {
            s = col[i];
            e = __expf(lrelu(ad + __ldg(asrc + s)));
        }
        psum += e;
        int cnt = min(32, re - base);
        for (int j = 0; j < cnt; j += NS) {
            int pj = j + group;
            float ej = __shfl_sync(0xffffffffu, e, pj & 31);
            int sj = __shfl_sync(0xffffffffu, s, pj & 31);
            if (!act || pj >= cnt) ej = 0.f;
            float4 hv = h4[(size_t)sj * NL + cid];
            acc.x += ej * hv.x;
            acc.y += ej * hv.y;
            acc.z += ej * hv.z;
            acc.w += ej * hv.w;
        }
    }

#pragma unroll
    for (int o = 16; o; o >>= 1) psum += __shfl_xor_sync(0xffffffffu, psum, o);

#pragma unroll
    for (int gq = 1; gq < NS; ++gq) {
        int srcl = cid + gq * NL;
        float tx = __shfl_sync(0xffffffffu, acc.x, srcl & 31);
        float ty = __shfl_sync(0xffffffffu, acc.y, srcl & 31);
        float tz = __shfl_sync(0xffffffffu, acc.z, srcl & 31);
        float tw = __shfl_sync(0xffffffffu, acc.w, srcl & 31);
        if (lane < NL) {
            acc.x += tx;
            acc.y += ty;
            acc.z += tz;
            acc.w += tw;
        }
    }

    float es = __expf(lrelu(ad + __ldg(asrc + d)));
    psum += es;

    float4 v = make_float4(0.f, 0.f, 0.f, 0.f);
    if (lane < NL) {
        float4 hv = h4[(size_t)d * NL + cid];
        float inv = 1.0f / psum;
        v.x = (acc.x + es * hv.x) * inv;
        v.y = (acc.y + es * hv.y) * inv;
        v.z = (acc.z + es * hv.z) * inv;
        v.w = (acc.w + es * hv.w) * inv;
    }

    if (LSM) {
        float vm = -1e30f;
        if (lane < NL) vm = fmaxf(fmaxf(v.x, v.y), fmaxf(v.z, v.w));
#pragma unroll
        for (int o = 16; o; o >>= 1) vm = fmaxf(vm, __shfl_xor_sync(0xffffffffu, vm, o));
        float se = 0.f;
        if (lane < NL)
            se = __expf(v.x - vm) + __expf(v.y - vm) + __expf(v.z - vm) + __expf(v.w - vm);
#pragma unroll
        for (int o = 16; o; o >>= 1) se += __shfl_xor_sync(0xffffffffu, se, o);
        float l = vm + logf(se);
        if (lane < NL) {
            v.x -= l;
            v.y -= l;
            v.z -= l;
            v.w -= l;
            reinterpret_cast<float4*>(out)[(size_t)d * NL + cid] = v;
        }
    } else {
        if (lane < NL) {
            if (RELU) {
                v.x = fmaxf(v.x, 0.f);
                v.y = fmaxf(v.y, 0.f);
                v.z = fmaxf(v.z, 0.f);
                v.w = fmaxf(v.w, 0.f);
            }
            reinterpret_cast<float4*>(out)[(size_t)d * NL + cid] = v;
        }
    }
}

// ---------------- launch ----------------
extern "C" void kernel_launch(void* const* d_in, const int* in_sizes, int n_in,
                              void* d_out, int out_size) {
    (void)in_sizes;
    (void)n_in;
    (void)out_size;
    const float* x    = (const float*)d_in[0];
    const int*   ei   = (const int*)d_in[1];
    const float* W0   = (const float*)d_in[2];
    const float* att0 = (const float*)d_in[3];
    const float* W1   = (const float*)d_in[4];
    const float* att1 = (const float*)d_in[5];
    float* out = (float*)d_out;

    void *p;
    float *h0, *h1, *h2, *adst, *asrc;
    int *rowptr, *cursor, *colp, *bsum;
    cudaGetSymbolAddress(&p, g_h0);     h0 = (float*)p;
    cudaGetSymbolAddress(&p, g_h1);     h1 = (float*)p;
    cudaGetSymbolAddress(&p, g_h2);     h2 = (float*)p;
    cudaGetSymbolAddress(&p, g_adst);   adst = (float*)p;
    cudaGetSymbolAddress(&p, g_asrc);   asrc = (float*)p;
    cudaGetSymbolAddress(&p, g_rowptr); rowptr = (int*)p;
    cudaGetSymbolAddress(&p, g_cursor); cursor = (int*)p;
    cudaGetSymbolAddress(&p, g_col);    colp = (int*)p;
    cudaGetSymbolAddress(&p, g_bsum);   bsum = (int*)p;

    cudaFuncSetAttribute(gemm1_mma_kernel,
                         cudaFuncAttributeMaxDynamicSharedMemorySize, SM_TOT);
    cudaFuncSetAttribute(gemm2_mma_kernel,
                         cudaFuncAttributeMaxDynamicSharedMemorySize, S2_TOT);

    const int TB = 256;
    int warp_blocks = (NN * 32 + TB - 1) / TB; // 12500

    cudaMemsetAsync(cursor, 0, NN * sizeof(int));
    cudaMemsetAsync(bsum, 0, 128 * sizeof(int));

    // Layer-1 GEMM (warp mma.sync) with embedded degree histogram
    gemm1_mma_kernel<<<GB1, TB, SM_TOT>>>(x, W0, att0, h0, adst, asrc, ei, cursor);

    // CSR finalize: one-kernel scan (decoupled lookback) + scatter
    scan_fused_kernel<<<NBLK, 1024>>>(cursor, rowptr, cursor, bsum);
    scatter_kernel<<<(EE / 8 + TB - 1) / TB, TB>>>(ei, cursor, colp);

    // Layer 1 aggregation: 64ch, relu
    aggregate_kernel<64, true, false><<<warp_blocks, TB>>>(h0, adst, asrc, rowptr, colp, h1);

    // Layer 2: 64 -> 40 (warp mma.sync), then fused log_softmax aggregation
    gemm2_mma_kernel<<<GB1, TB, S2_TOT>>>(h1, W1, att1, h2, adst, asrc);
    aggregate_kernel<40, false, true><<<warp_blocks, TB>>>(h2, adst, asrc, rowptr, colp, out);
}